// round 9
// baseline (speedup 1.0000x reference)
#include <cuda_runtime.h>

// Decoder_predict: batched greedy goals-NMS.  B=256, N=4096, T=30, K=6.
// scores = class * centerness, thr^2 = 4.0.
//
// V9: V8 (byte diet + overlapped coord gather + flag-pipelined outputs)
// with the serial phase converted to pure 32-bit keys.
//  - Phase 1 (all 16 warps): read only cls+cent (8 MB total), per-warp top-6
//    by u32 score bits; ballot lowest-lane + lowest-slot = exact lowest-index
//    tie-break; winning lane immediately gathers that survivor's float2 coord
//    (latency overlapped with remaining rounds). Survivors -> smem arrays
//    skey (u32), sidx (int), scoord (float2), slot = wid*6 + r.
//  - Slot order == original-index order for equal scores (warps own
//    contiguous index ranges; equal scores extracted lowest-index-first), so
//    phase 2 tie-breaks by lowest slot: 3 ballots, no u64 shuffles at all.
//  - Phase 2 (warp 0): 6 greedy rounds over 96 survivors (3/lane), u32
//    butterflies; lane 0 writes probs/goals to global directly and releases
//    per-round flags; warps 1..6 gather their traj row as soon as their
//    round resolves. Single __syncthreads in the kernel.

#define NMS_B 256
#define NMS_N 4096
#define NMS_T 30
#define NMS_K 6
#define NMS_THR2 4.0f
#define THREADS 512
#define WARPS 16
#define SURV (WARPS * NMS_K)   // 96

__global__ __launch_bounds__(THREADS, 2)
void nms_goals_kernel(const float* __restrict__ coord,   // [B,1,N,2]
                      const float* __restrict__ cls,     // [B,1,N]
                      const float* __restrict__ traj,    // [B,1,N,T,2]
                      const float* __restrict__ cent,    // [B,1,N]
                      float* __restrict__ out)
{
    const int b    = blockIdx.x;
    const int tid  = threadIdx.x;
    const int wid  = tid >> 5;
    const int lane = tid & 31;

    __shared__ unsigned skey[SURV];     // score bits, 0 = empty
    __shared__ int      sidx[SURV];     // original index
    __shared__ float2   scoord[SURV];
    __shared__ int      sel_i[NMS_K];
    __shared__ volatile int flags[NMS_K];

    if (tid < NMS_K) flags[tid] = 0;

    // ---- Phase 1: scores only, 8 contiguous candidates per thread. ----
    {
        const float4* s4   = (const float4*)(cls  + (size_t)b * NMS_N);
        const float4* e4   = (const float4*)(cent + (size_t)b * NMS_N);
        const float2* cptr = (const float2*)(coord + (size_t)b * NMS_N * 2);

        const float4 sa = s4[2 * tid];
        const float4 sb = s4[2 * tid + 1];
        const float4 ea = e4[2 * tid];
        const float4 eb = e4[2 * tid + 1];

        unsigned sc[8];
        sc[0] = __float_as_uint(sa.x * ea.x);
        sc[1] = __float_as_uint(sa.y * ea.y);
        sc[2] = __float_as_uint(sa.z * ea.z);
        sc[3] = __float_as_uint(sa.w * ea.w);
        sc[4] = __float_as_uint(sb.x * eb.x);
        sc[5] = __float_as_uint(sb.y * eb.y);
        sc[6] = __float_as_uint(sb.z * eb.z);
        sc[7] = __float_as_uint(sb.w * eb.w);

        unsigned tmax = sc[0];
#pragma unroll
        for (int j = 1; j < 8; j++) tmax = max(tmax, sc[j]);

#pragma unroll
        for (int r = 0; r < NMS_K; r++) {
            unsigned m = tmax;
#pragma unroll
            for (int off = 16; off > 0; off >>= 1)
                m = max(m, __shfl_xor_sync(0xFFFFFFFFu, m, off));

            if (m == 0u) {
                if (lane == 0) skey[wid * NMS_K + r] = 0u;   // empty slot
            } else {
                const bool mine = (tmax == m);
                const unsigned bal = __ballot_sync(0xFFFFFFFFu, mine);
                const int wl = __ffs(bal) - 1;   // lowest lane = lowest idx
                if (lane == wl) {
                    int jm = 7;
#pragma unroll
                    for (int j = 7; j >= 0; j--)
                        if (sc[j] == m) jm = j;   // lowest slot = lowest idx
                    const int idx = 8 * tid + jm;
                    const int s   = wid * NMS_K + r;
                    skey[s]   = m;
                    sidx[s]   = idx;
                    scoord[s] = cptr[idx];        // overlapped coord gather
#pragma unroll
                    for (int j = 0; j < 8; j++) if (sc[j] == m) sc[j] = 0u;
                    tmax = sc[0];
#pragma unroll
                    for (int j = 1; j < 8; j++) tmax = max(tmax, sc[j]);
                }
            }
        }
    }
    __syncthreads();    // the only block barrier

    // ---- Phase 2: warp 0 greedy NMS over 96 survivors (3/lane, u32). ----
    if (wid == 0) {
        unsigned vp[3];
        float vx[3], vy[3];
#pragma unroll
        for (int h = 0; h < 3; h++) {
            vp[h] = skey[lane + 32 * h];
            const float2 c = scoord[lane + 32 * h];
            vx[h] = c.x;  vy[h] = c.y;
        }

        float* out_prob = out + (size_t)NMS_B * NMS_K * NMS_T * 2;
        float* out_goal = out_prob + (size_t)NMS_B * NMS_K;
        float  s0 = 0.0f;   // round-0 score, kept by all lanes for fallback

#pragma unroll
        for (int r = 0; r < NMS_K; r++) {
            unsigned m = max(max(vp[0], vp[1]), vp[2]);
#pragma unroll
            for (int off = 16; off > 0; off >>= 1)
                m = max(m, __shfl_xor_sync(0xFFFFFFFFu, m, off));

            if (m == 0u) {
                // Fallback slot: reference keeps sel_idx = 0 -> round-0 point's
                // score/traj, goal (0,0).
                if (lane == 0) {
                    sel_i[r] = -1;
                    out_prob[(size_t)b * NMS_K + r]           = s0;
                    out_goal[((size_t)b * NMS_K + r) * 2 + 0] = 0.0f;
                    out_goal[((size_t)b * NMS_K + r) * 2 + 1] = 0.0f;
                    __threadfence_block();
                    flags[r] = 1;
                }
            } else {
                // Lowest-slot tie-break: prefer h=0 block, then h=1, then h=2;
                // lowest lane within the block.  slot = wl + 32*hsel.
                const unsigned b0 = __ballot_sync(0xFFFFFFFFu, vp[0] == m);
                const unsigned b1 = __ballot_sync(0xFFFFFFFFu, vp[1] == m);
                const unsigned b2 = __ballot_sync(0xFFFFFFFFu, vp[2] == m);
                int hsel, wl;
                if (b0)      { hsel = 0; wl = __ffs(b0) - 1; }
                else if (b1) { hsel = 1; wl = __ffs(b1) - 1; }
                else         { hsel = 2; wl = __ffs(b2) - 1; }

                const float fx = (hsel == 0) ? vx[0] : ((hsel == 1) ? vx[1] : vx[2]);
                const float fy = (hsel == 0) ? vy[0] : ((hsel == 1) ? vy[1] : vy[2]);
                const float px = __shfl_sync(0xFFFFFFFFu, fx, wl);
                const float py = __shfl_sync(0xFFFFFFFFu, fy, wl);
                if (r == 0) s0 = __uint_as_float(m);

                if (lane == 0) {
                    sel_i[r] = sidx[wl + 32 * hsel];
                    out_prob[(size_t)b * NMS_K + r]           = __uint_as_float(m);
                    out_goal[((size_t)b * NMS_K + r) * 2 + 0] = px;
                    out_goal[((size_t)b * NMS_K + r) * 2 + 1] = py;
                    __threadfence_block();
                    flags[r] = 1;     // release this round's selection
                }
                // Suppress survivors within thr (incl. the winner itself).
#pragma unroll
                for (int h = 0; h < 3; h++) {
                    const float dx = vx[h] - px;
                    const float dy = vy[h] - py;
                    if (dx * dx + dy * dy < NMS_THR2) vp[h] = 0u;
                }
            }
            __syncwarp();
        }
    }
    // ---- Phase 3: traj gathers start as soon as their round resolves. ----
    else if (wid <= NMS_K) {            // warps 1..6 -> traj row (wid-1)
        const int r = wid - 1;
        while (flags[r] == 0) { }
        __threadfence_block();
        const int sr = sel_i[r];
        int src = (sr >= 0) ? sr : sel_i[0];
        if (src < 0) src = 0;           // unreachable; memory safety only
        if (lane < 15) {
            ((float4*)out)[((size_t)b * NMS_K + r) * 15 + lane] =
                ((const float4*)traj)[((size_t)b * NMS_N + src) * 15 + lane];
        }
    }
    // warps 7..15: done after phase 1.
}

extern "C" void kernel_launch(void* const* d_in, const int* in_sizes, int n_in,
                              void* d_out, int out_size) {
    const float* coord = (const float*)d_in[0];  // outputs_coord     [B,1,N,2]
    const float* cls   = (const float*)d_in[1];  // outputs_class     [B,1,N]
    const float* traj  = (const float*)d_in[2];  // outputs_traj      [B,1,N,T,2]
    const float* cent  = (const float*)d_in[3];  // outputs_centerness[B,1,N]
    float* out = (float*)d_out;

    nms_goals_kernel<<<NMS_B, THREADS>>>(coord, cls, traj, cent, out);
}